// round 14
// baseline (speedup 1.0000x reference)
#include <cuda_runtime.h>
#include <cuda_bf16.h>
#include <cstdint>

#define BB 2
#define HH 16
#define SS 2048
#define DD 64
#define NTHREADS 256
#define CTX_ELEMS (BB*HH*SS*DD)
#define NHEADS 32
#define NKT 16                 // key tiles of 128
#define TILE_BYTES 32768       // frag-tile image (hi+lo packed)
#define ETILE_BYTES 65536      // E scratch tile (128x128 bf16 hi+lo)
#define EXPC 0.18033688011112042f   // 0.125 * log2(e)
#define MASK_WORDS (BB*SS*64)       // 262144 u32 words

// gmem scratch
__device__ __align__(16) unsigned char g_qf[(size_t)NHEADS*16*TILE_BYTES];
__device__ __align__(16) unsigned char g_kf[(size_t)NHEADS*NKT*TILE_BYTES];
__device__ __align__(16) unsigned char g_vf[(size_t)NHEADS*NKT*TILE_BYTES];
__device__ __align__(16) unsigned char g_es[(size_t)512*NKT*ETILE_BYTES];  // per-CTA E tiles
__device__ __align__(16) unsigned int  g_maskbits[MASK_WORDS];

__device__ __forceinline__ uint32_t pack2hi(float a, float b) {
    __nv_bfloat16 ha = __float2bfloat16(a), hb = __float2bfloat16(b);
    return (uint32_t)__bfloat16_as_ushort(ha) | ((uint32_t)__bfloat16_as_ushort(hb) << 16);
}
__device__ __forceinline__ uint32_t pack2lo(float a, float b) {
    __nv_bfloat16 ha = __float2bfloat16(a), hb = __float2bfloat16(b);
    __nv_bfloat16 la = __float2bfloat16(a - __bfloat162float(ha));
    __nv_bfloat16 lb = __float2bfloat16(b - __bfloat162float(hb));
    return (uint32_t)__bfloat16_as_ushort(la) | ((uint32_t)__bfloat16_as_ushort(lb) << 16);
}
__device__ __forceinline__ float2 unp2(uint32_t u) {
    __nv_bfloat162 h = *reinterpret_cast<__nv_bfloat162*>(&u);
    return __bfloat1622float2(h);
}

// ---- merged prepass: fragment images (blocks 0..1535) + mask bits (1536..2559) ----
__global__ void prepass_kernel(const float* __restrict__ Q,
                               const float* __restrict__ K,
                               const float* __restrict__ V,
                               const int* __restrict__ M)
{
    const int bx = blockIdx.x;
    if (bx >= 1536) {
        const int w = (bx - 1536) * NTHREADS + threadIdx.x;   // 262144 words total
        const int* src = M + (size_t)w * 32;
        unsigned int bits = 0;
        #pragma unroll
        for (int j = 0; j < 32; j++) bits |= (src[j] != 0 ? 1u : 0u) << j;
        g_maskbits[w] = bits;
        return;
    }
    const int which = bx >> 9;               // 0=Q 1=K 2=V
    const int chunk = bx & 511;              // head*16 + sub
    const int head = chunk >> 4, sub = chunk & 15;
    const float* S_ = (which == 0 ? Q : which == 1 ? K : V) + (size_t)head * SS * DD;
    unsigned char* dst = (which == 0 ? g_qf : which == 1 ? g_kf : g_vf) + (size_t)chunk * TILE_BYTES;

    for (int i = threadIdx.x; i < 8192; i += NTHREADS) {
        float f0, f1; bool lo;
        if (which == 0) {
            int word = i & 7, lane = (i >> 3) & 31, kt = (i >> 8) & 3, mt = i >> 10;
            int ai = word & 3; lo = word >= 4;
            int r = (lane >> 2) + ((ai & 1) ? 8 : 0);
            int c = (lane & 3) * 2 + ((ai >= 2) ? 8 : 0);
            int row = sub * 128 + mt * 16 + r, col = kt * 16 + c;
            f0 = S_[(size_t)row * DD + col]; f1 = S_[(size_t)row * DD + col + 1];
        } else if (which == 1) {
            int word = i & 3, lane = (i >> 2) & 31, kt = (i >> 7) & 3, ntl = (i >> 9) & 15;
            int bsel = word & 1; lo = word >= 2;
            int key = (sub * 16 + ntl) * 8 + (lane >> 2);
            int dim = kt * 16 + (lane & 3) * 2 + (bsel ? 8 : 0);
            f0 = S_[(size_t)key * DD + dim]; f1 = S_[(size_t)key * DD + dim + 1];
        } else {
            int word = i & 3, lane = (i >> 2) & 31, ktl = (i >> 7) & 7, nt = (i >> 10) & 7;
            int bsel = word & 1; lo = word >= 2;
            int key = (sub * 8 + ktl) * 16 + (lane & 3) * 2 + (bsel ? 8 : 0);
            int dim = nt * 8 + (lane >> 2);
            f0 = S_[(size_t)key * DD + dim]; f1 = S_[(size_t)(key + 1) * DD + dim];
        }
        ((uint32_t*)dst)[i] = lo ? pack2lo(f0, f1) : pack2hi(f0, f1);
    }
}

// ---- main ----
__device__ __forceinline__ void mma_bf16(float d[4], const uint32_t a[4],
                                         uint32_t b0, uint32_t b1) {
    asm volatile("mma.sync.aligned.m16n8k16.row.col.f32.bf16.bf16.f32 "
        "{%0,%1,%2,%3}, {%4,%5,%6,%7}, {%8,%9}, {%0,%1,%2,%3};"
        : "+f"(d[0]), "+f"(d[1]), "+f"(d[2]), "+f"(d[3])
        : "r"(a[0]), "r"(a[1]), "r"(a[2]), "r"(a[3]), "r"(b0), "r"(b1));
}

__global__ __launch_bounds__(NTHREADS, 2)
void attn_main(float* __restrict__ out)
{
    __shared__ float sSum[128];
    const int tid = threadIdx.x, w = tid >> 5, lane = tid & 31;
    const int head = blockIdx.x >> 4, qblk = blockIdx.x & 15;
    const int b = head >> 4;
    const int q0 = qblk * 128;
    const int r0 = 16 * w + (lane >> 2);      // local row (this lane: r0 and r0+8)
    const int cq = (lane & 3) * 2;

    // Q fragments resident
    uint32_t qh[4][4], ql[4][4];
    {
        const unsigned char* qc = g_qf + (size_t)(head * 16 + qblk) * TILE_BYTES;
        #pragma unroll
        for (int kt = 0; kt < 4; kt++) {
            const unsigned char* p = qc + (size_t)(((w * 4 + kt) * 32 + lane) * 32);
            uint4 h = *(const uint4*)p, l = *(const uint4*)(p + 16);
            qh[kt][0] = h.x; qh[kt][1] = h.y; qh[kt][2] = h.z; qh[kt][3] = h.w;
            ql[kt][0] = l.x; ql[kt][1] = l.y; ql[kt][2] = l.z; ql[kt][3] = l.w;
        }
    }
    const unsigned char* mrow0 = (const unsigned char*)g_maskbits + (size_t)(b * SS + q0 + r0) * 256;
    const unsigned char* mrow1 = mrow0 + 8 * 256;
    const unsigned char* kbase = g_kf + (size_t)head * NKT * TILE_BYTES;
    const unsigned char* vbase = g_vf + (size_t)head * NKT * TILE_BYTES;
    unsigned char* esbase = g_es + (size_t)blockIdx.x * NKT * ETILE_BYTES;

    // ================= pass A: QK + exp -> rowsums + E scratch =================
    float rs0 = 0.f, rs1 = 0.f;
    for (int t = 0; t < 16; t++) {
        const unsigned char* Kb = kbase + (size_t)t * TILE_BYTES;
        unsigned char* et = esbase + (size_t)t * ETILE_BYTES + w * 8192;
        uint4 mA = *(const uint4*)(mrow0 + t * 16);
        uint4 mB = *(const uint4*)(mrow1 + t * 16);
        const uint32_t mwA[4] = {mA.x, mA.y, mA.z, mA.w};
        const uint32_t mwB[4] = {mB.x, mB.y, mB.z, mB.w};
        float pe0, pe1, pe2, pe3;
        #pragma unroll
        for (int j = 0; j < 16; j++) {
            float d[4] = {0.f, 0.f, 0.f, 0.f};
            #pragma unroll
            for (int kt = 0; kt < 4; kt++) {
                uint4 bb = *(const uint4*)(Kb + ((j * 4 + kt) * 32 + lane) * 16);
                mma_bf16(d, qh[kt], bb.x, bb.y);
                mma_bf16(d, ql[kt], bb.x, bb.y);
                mma_bf16(d, qh[kt], bb.z, bb.w);
            }
            const int sh = 8 * (j & 3) + cq;
            const uint32_t ma = mwA[j >> 2] >> sh, mb2 = mwB[j >> 2] >> sh;
            float e0 = (ma  & 1) ? 0.f : exp2f(d[0] * EXPC);
            float e1 = (ma  & 2) ? 0.f : exp2f(d[1] * EXPC);
            float e2 = (mb2 & 1) ? 0.f : exp2f(d[2] * EXPC);
            float e3 = (mb2 & 2) ? 0.f : exp2f(d[3] * EXPC);
            rs0 += e0 + e1;  rs1 += e2 + e3;
            if ((j & 1) == 0) { pe0 = e0; pe1 = e1; pe2 = e2; pe3 = e3; }
            else {
                uint4 hi4, lo4;
                hi4.x = pack2hi(pe0, pe1); hi4.y = pack2hi(pe2, pe3);
                hi4.z = pack2hi(e0, e1);   hi4.w = pack2hi(e2, e3);
                lo4.x = pack2lo(pe0, pe1); lo4.y = pack2lo(pe2, pe3);
                lo4.z = pack2lo(e0, e1);   lo4.w = pack2lo(e2, e3);
                unsigned char* ep = et + (j >> 1) * 1024 + lane * 16;
                *(uint4*)ep = hi4;
                *(uint4*)(ep + 512) = lo4;
            }
        }
    }
    rs0 += __shfl_xor_sync(0xFFFFFFFFu, rs0, 1); rs0 += __shfl_xor_sync(0xFFFFFFFFu, rs0, 2);
    rs1 += __shfl_xor_sync(0xFFFFFFFFu, rs1, 1); rs1 += __shfl_xor_sync(0xFFFFFFFFu, rs1, 2);
    if ((lane & 3) == 0) { sSum[r0] = rs0; sSum[r0 + 8] = rs1; }
    __syncthreads();
    const float inv0 = 1.0f / sSum[r0];
    const float inv1 = 1.0f / sSum[r0 + 8];

    // ================= pass B: load E, write att (hi+lo), PV =================
    float dacc[8][4];
    #pragma unroll
    for (int nt = 0; nt < 8; nt++) { dacc[nt][0]=0.f; dacc[nt][1]=0.f; dacc[nt][2]=0.f; dacc[nt][3]=0.f; }
    float* att = out + (size_t)CTX_ELEMS + (size_t)head * SS * SS;
    for (int t = 0; t < 16; t++) {
        const unsigned char* Eb = esbase + (size_t)t * ETILE_BYTES + w * 8192;
        const unsigned char* Vb = vbase + (size_t)t * TILE_BYTES;
        #pragma unroll
        for (int ktl = 0; ktl < 8; ktl++) {
            uint4 eh4 = *(const uint4*)(Eb + ktl * 1024 + lane * 16);
            uint4 el4 = *(const uint4*)(Eb + ktl * 1024 + 512 + lane * 16);
            // att output: p = (e_hi + e_lo) * inv — full precision reconstruction
            {
                float* a0 = att + (size_t)(q0 + r0) * SS + t * 128 + 16 * ktl + cq;
                float2 h0 = unp2(eh4.x), h1 = unp2(eh4.y), h2 = unp2(eh4.z), h3 = unp2(eh4.w);
                float2 l0 = unp2(el4.x), l1 = unp2(el4.y), l2 = unp2(el4.z), l3 = unp2(el4.w);
                *(float2*)a0 =
                    make_float2((h0.x + l0.x) * inv0, (h0.y + l0.y) * inv0);
                *(float2*)(a0 + 8 * (size_t)SS) =
                    make_float2((h1.x + l1.x) * inv1, (h1.y + l1.y) * inv1);
                *(float2*)(a0 + 8) =
                    make_float2((h2.x + l2.x) * inv0, (h2.y + l2.y) * inv0);
                *(float2*)(a0 + 8 * (size_t)SS + 8) =
                    make_float2((h3.x + l3.x) * inv1, (h3.y + l3.y) * inv1);
            }
            const uint32_t eh[4] = {eh4.x, eh4.y, eh4.z, eh4.w};
            const uint32_t el[4] = {el4.x, el4.y, el4.z, el4.w};
            #pragma unroll
            for (int nt = 0; nt < 8; nt++) {
                uint4 vb = *(const uint4*)(Vb + ((nt * 8 + ktl) * 32 + lane) * 16);
                mma_bf16(dacc[nt], eh, vb.x, vb.y);
                mma_bf16(dacc[nt], el, vb.x, vb.y);
                mma_bf16(dacc[nt], eh, vb.z, vb.w);
            }
        }
    }

    // context epilogue: fold inv here (ctx = inv * (E @ V))
    float* ctx = out + (size_t)head * SS * DD;
    #pragma unroll
    for (int nt = 0; nt < 8; nt++) {
        const int col = 8 * nt + cq;
        *(float2*)(ctx + (size_t)(q0 + r0) * DD + col) =
            make_float2(dacc[nt][0] * inv0, dacc[nt][1] * inv0);
        *(float2*)(ctx + (size_t)(q0 + r0 + 8) * DD + col) =
            make_float2(dacc[nt][2] * inv1, dacc[nt][3] * inv1);
    }
}

extern "C" void kernel_launch(void* const* d_in, const int* in_sizes, int n_in,
                              void* d_out, int out_size)
{
    (void)in_sizes; (void)n_in; (void)out_size;
    const float* Q = (const float*)d_in[0];
    const float* K = (const float*)d_in[1];
    const float* V = (const float*)d_in[2];
    const int*   M = (const int*)d_in[3];
    float* out = (float*)d_out;

    prepass_kernel<<<2560, NTHREADS>>>(Q, K, V, M);
    attn_main<<<NHEADS * 16, NTHREADS>>>(out);
}

// round 15
// speedup vs baseline: 1.2560x; 1.2560x over previous
#include <cuda_runtime.h>
#include <cuda_bf16.h>
#include <cstdint>

#define BB 2
#define HH 16
#define SS 2048
#define DD 64
#define NTHREADS 256
#define CTX_ELEMS (BB*HH*SS*DD)
#define NHEADS 32
#define NT64 32                // key tiles of 64
#define QTILE_BYTES 32768      // Q frag image per 128-row block (hi+lo)
#define KTILE 16384            // K/V frag image per 64-key tile (hi+lo)
#define SMEM_DYN 65536         // K pp [0,32K) + V pp [32K,64K)
#define EXPC 0.18033688011112042f   // 0.125 * log2(e)
#define MASK_WORDS (BB*SS*64)

__device__ __align__(16) unsigned char g_qf[(size_t)NHEADS*16*QTILE_BYTES];
__device__ __align__(16) unsigned char g_kf[(size_t)NHEADS*NT64*KTILE];
__device__ __align__(16) unsigned char g_vf[(size_t)NHEADS*NT64*KTILE];
__device__ __align__(16) unsigned int  g_maskbits[MASK_WORDS];

__device__ __forceinline__ uint32_t pack2hi(float a, float b) {
    __nv_bfloat16 ha = __float2bfloat16(a), hb = __float2bfloat16(b);
    return (uint32_t)__bfloat16_as_ushort(ha) | ((uint32_t)__bfloat16_as_ushort(hb) << 16);
}
__device__ __forceinline__ uint32_t pack2lo(float a, float b) {
    __nv_bfloat16 ha = __float2bfloat16(a), hb = __float2bfloat16(b);
    __nv_bfloat16 la = __float2bfloat16(a - __bfloat162float(ha));
    __nv_bfloat16 lb = __float2bfloat16(b - __bfloat162float(hb));
    return (uint32_t)__bfloat16_as_ushort(la) | ((uint32_t)__bfloat16_as_ushort(lb) << 16);
}

// ---- prepass: Q(512) K(1024) V(1024) mask(1024) blocks ----
__global__ void prepass_kernel(const float* __restrict__ Q,
                               const float* __restrict__ K,
                               const float* __restrict__ V,
                               const int* __restrict__ M)
{
    const int bx = blockIdx.x;
    if (bx >= 2560) {
        const int w = (bx - 2560) * NTHREADS + threadIdx.x;
        const int* src = M + (size_t)w * 32;
        unsigned int bits = 0;
        #pragma unroll
        for (int j = 0; j < 32; j++) bits |= (src[j] != 0 ? 1u : 0u) << j;
        g_maskbits[w] = bits;
        return;
    }
    if (bx < 512) {
        // Q frag image: chunk = head*16 + sub (128-row block)
        const int chunk = bx, head = chunk >> 4, sub = chunk & 15;
        const float* S_ = Q + (size_t)head * SS * DD;
        uint32_t* dst = (uint32_t*)(g_qf + (size_t)chunk * QTILE_BYTES);
        for (int i = threadIdx.x; i < 8192; i += NTHREADS) {
            int word = i & 7, lane = (i >> 3) & 31, kt = (i >> 8) & 3, mt = i >> 10;
            int ai = word & 3; bool lo = word >= 4;
            int r = (lane >> 2) + ((ai & 1) ? 8 : 0);
            int c = (lane & 3) * 2 + ((ai >= 2) ? 8 : 0);
            int row = sub * 128 + mt * 16 + r, col = kt * 16 + c;
            float f0 = S_[(size_t)row * DD + col], f1 = S_[(size_t)row * DD + col + 1];
            dst[i] = lo ? pack2lo(f0, f1) : pack2hi(f0, f1);
        }
        return;
    }
    if (bx < 1536) {
        // K frag image: chunk = head*32 + sub (64-key tile)
        const int chunk = bx - 512, head = chunk >> 5, sub = chunk & 31;
        const float* S_ = K + (size_t)head * SS * DD;
        uint32_t* dst = (uint32_t*)(g_kf + (size_t)chunk * KTILE);
        for (int i = threadIdx.x; i < 4096; i += NTHREADS) {
            int word = i & 3, lane = (i >> 2) & 31, kt = (i >> 7) & 3, ntl = (i >> 9) & 7;
            int bsel = word & 1; bool lo = word >= 2;
            int key = sub * 64 + ntl * 8 + (lane >> 2);
            int dim = kt * 16 + (lane & 3) * 2 + (bsel ? 8 : 0);
            float f0 = S_[(size_t)key * DD + dim], f1 = S_[(size_t)key * DD + dim + 1];
            dst[i] = lo ? pack2lo(f0, f1) : pack2hi(f0, f1);
        }
        return;
    }
    {
        // V frag image: chunk = head*32 + sub (64-key tile)
        const int chunk = bx - 1536, head = chunk >> 5, sub = chunk & 31;
        const float* S_ = V + (size_t)head * SS * DD;
        uint32_t* dst = (uint32_t*)(g_vf + (size_t)chunk * KTILE);
        for (int i = threadIdx.x; i < 4096; i += NTHREADS) {
            int word = i & 3, lane = (i >> 2) & 31, ktl = (i >> 7) & 3, nt = (i >> 9) & 7;
            int bsel = word & 1; bool lo = word >= 2;
            int key = sub * 64 + ktl * 16 + (lane & 3) * 2 + (bsel ? 8 : 0);
            int dim = nt * 8 + (lane >> 2);
            float f0 = S_[(size_t)key * DD + dim], f1 = S_[(size_t)(key + 1) * DD + dim];
            dst[i] = lo ? pack2lo(f0, f1) : pack2hi(f0, f1);
        }
    }
}

// ---- main ----
__device__ __forceinline__ uint32_t smem_u32(const void* p) {
    uint32_t a;
    asm("{ .reg .u64 t; cvta.to.shared.u64 t, %1; cvt.u32.u64 %0, t; }" : "=r"(a) : "l"(p));
    return a;
}
__device__ __forceinline__ void cp16(uint32_t s, const void* g) {
    asm volatile("cp.async.cg.shared.global [%0], [%1], 16;" :: "r"(s), "l"(g));
}
__device__ __forceinline__ void mma_bf16(float d[4], const uint32_t a[4],
                                         uint32_t b0, uint32_t b1) {
    asm volatile("mma.sync.aligned.m16n8k16.row.col.f32.bf16.bf16.f32 "
        "{%0,%1,%2,%3}, {%4,%5,%6,%7}, {%8,%9}, {%0,%1,%2,%3};"
        : "+f"(d[0]), "+f"(d[1]), "+f"(d[2]), "+f"(d[3])
        : "r"(a[0]), "r"(a[1]), "r"(a[2]), "r"(a[3]), "r"(b0), "r"(b1));
}
__device__ __forceinline__ void qk_one(const unsigned char* Kb, int lane, int j,
                                       const uint32_t qh[4][4], const uint32_t ql[4][4],
                                       float d[4])
{
    d[0] = d[1] = d[2] = d[3] = 0.f;
    #pragma unroll
    for (int kt = 0; kt < 4; kt++) {
        uint4 bb = *(const uint4*)(Kb + ((j * 4 + kt) * 32 + lane) * 16);
        mma_bf16(d, qh[kt], bb.x, bb.y);
        mma_bf16(d, ql[kt], bb.x, bb.y);
        mma_bf16(d, qh[kt], bb.z, bb.w);
    }
}

__global__ __launch_bounds__(NTHREADS, 2)
void attn_main(float* __restrict__ out)
{
    extern __shared__ unsigned char smem[];  // K pp [0,32K), V pp [32K,64K)
    __shared__ float sSum[128];
    const uint32_t sb = smem_u32(smem);
    const int tid = threadIdx.x, w = tid >> 5, lane = tid & 31;
    const int head = blockIdx.x >> 4, qblk = blockIdx.x & 15;
    const int b = head >> 4;
    const int q0 = qblk * 128;
    const int r0 = 16 * w + (lane >> 2);
    const int cq = (lane & 3) * 2;

    // Q fragments resident
    uint32_t qh[4][4], ql[4][4];
    {
        const unsigned char* qc = g_qf + (size_t)(head * 16 + qblk) * QTILE_BYTES;
        #pragma unroll
        for (int kt = 0; kt < 4; kt++) {
            const unsigned char* p = qc + (size_t)(((w * 4 + kt) * 32 + lane) * 32);
            uint4 h = *(const uint4*)p, l = *(const uint4*)(p + 16);
            qh[kt][0] = h.x; qh[kt][1] = h.y; qh[kt][2] = h.z; qh[kt][3] = h.w;
            ql[kt][0] = l.x; ql[kt][1] = l.y; ql[kt][2] = l.z; ql[kt][3] = l.w;
        }
    }
    const unsigned char* mrow0 = (const unsigned char*)g_maskbits + (size_t)(b * SS + q0 + r0) * 256;
    const unsigned char* mrow1 = mrow0 + 8 * 256;
    const unsigned char* kbase = g_kf + (size_t)head * NT64 * KTILE;
    const unsigned char* vbase = g_vf + (size_t)head * NT64 * KTILE;

    // ================= pass A: rowsums =================
    {
        #pragma unroll
        for (int i = 0; i < 4; i++) cp16(sb + tid * 16 + i * 4096, kbase + tid * 16 + i * 4096);
        asm volatile("cp.async.commit_group;");
    }
    float rs0 = 0.f, rs1 = 0.f;
    for (int t = 0; t < NT64; t++) {
        if (t < NT64 - 1) {
            const unsigned char* src = kbase + (size_t)(t + 1) * KTILE;
            uint32_t d0 = sb + ((t + 1) & 1) * 16384;
            #pragma unroll
            for (int i = 0; i < 4; i++) cp16(d0 + tid * 16 + i * 4096, src + tid * 16 + i * 4096);
            asm volatile("cp.async.commit_group;");
            asm volatile("cp.async.wait_group 1;");
        } else {
            asm volatile("cp.async.wait_group 0;");
        }
        __syncthreads();
        const unsigned char* Kb = smem + (t & 1) * 16384;
        uint2 mA = *(const uint2*)(mrow0 + t * 8);
        uint2 mB = *(const uint2*)(mrow1 + t * 8);
        #pragma unroll
        for (int j = 0; j < 8; j++) {
            float d[4];
            qk_one(Kb, lane, j, qh, ql, d);
            const int sh = 8 * (j & 3) + cq;
            const uint32_t ma = ((j < 4) ? mA.x : mA.y) >> sh;
            const uint32_t mb2 = ((j < 4) ? mB.x : mB.y) >> sh;
            rs0 += ((ma  & 1) ? 0.f : exp2f(d[0] * EXPC)) + ((ma  & 2) ? 0.f : exp2f(d[1] * EXPC));
            rs1 += ((mb2 & 1) ? 0.f : exp2f(d[2] * EXPC)) + ((mb2 & 2) ? 0.f : exp2f(d[3] * EXPC));
        }
        __syncthreads();
    }
    rs0 += __shfl_xor_sync(0xFFFFFFFFu, rs0, 1); rs0 += __shfl_xor_sync(0xFFFFFFFFu, rs0, 2);
    rs1 += __shfl_xor_sync(0xFFFFFFFFu, rs1, 1); rs1 += __shfl_xor_sync(0xFFFFFFFFu, rs1, 2);
    if ((lane & 3) == 0) { sSum[r0] = rs0; sSum[r0 + 8] = rs1; }
    __syncthreads();
    const float inv0 = 1.0f / sSum[r0];
    const float inv1 = 1.0f / sSum[r0 + 8];

    // ================= pass B: recompute + att + PV (interleaved) =================
    float dacc[8][4];
    #pragma unroll
    for (int nt = 0; nt < 8; nt++) { dacc[nt][0]=0.f; dacc[nt][1]=0.f; dacc[nt][2]=0.f; dacc[nt][3]=0.f; }
    {
        #pragma unroll
        for (int i = 0; i < 4; i++) cp16(sb + tid * 16 + i * 4096, kbase + tid * 16 + i * 4096);
        #pragma unroll
        for (int i = 0; i < 4; i++) cp16(sb + 32768 + tid * 16 + i * 4096, vbase + tid * 16 + i * 4096);
        asm volatile("cp.async.commit_group;");
    }
    float* att = out + (size_t)CTX_ELEMS + (size_t)head * SS * SS;
    for (int t = 0; t < NT64; t++) {
        if (t < NT64 - 1) {
            const unsigned char* sk = kbase + (size_t)(t + 1) * KTILE;
            const unsigned char* sv = vbase + (size_t)(t + 1) * KTILE;
            uint32_t dk = sb + ((t + 1) & 1) * 16384;
            uint32_t dv = sb + 32768 + ((t + 1) & 1) * 16384;
            #pragma unroll
            for (int i = 0; i < 4; i++) cp16(dk + tid * 16 + i * 4096, sk + tid * 16 + i * 4096);
            #pragma unroll
            for (int i = 0; i < 4; i++) cp16(dv + tid * 16 + i * 4096, sv + tid * 16 + i * 4096);
            asm volatile("cp.async.commit_group;");
            asm volatile("cp.async.wait_group 1;");
        } else {
            asm volatile("cp.async.wait_group 0;");
        }
        __syncthreads();
        const unsigned char* Kb = smem + (t & 1) * 16384;
        const unsigned char* Vb = smem + 32768 + (t & 1) * 16384;
        uint2 mA = *(const uint2*)(mrow0 + t * 8);
        uint2 mB = *(const uint2*)(mrow1 + t * 8);
        #pragma unroll
        for (int u = 0; u < 4; u++) {
            const int j0 = 2 * u, j1 = 2 * u + 1;
            float d0[4], d1[4];
            qk_one(Kb, lane, j0, qh, ql, d0);
            qk_one(Kb, lane, j1, qh, ql, d1);
            const int sh0 = 8 * (j0 & 3) + cq, sh1 = 8 * (j1 & 3) + cq;
            const uint32_t ma0 = ((j0 < 4) ? mA.x : mA.y) >> sh0;
            const uint32_t mb0 = ((j0 < 4) ? mB.x : mB.y) >> sh0;
            const uint32_t ma1 = ((j1 < 4) ? mA.x : mA.y) >> sh1;
            const uint32_t mb1 = ((j1 < 4) ? mB.x : mB.y) >> sh1;
            float p0 = (ma0 & 1) ? 0.f : exp2f(d0[0] * EXPC) * inv0;
            float p1 = (ma0 & 2) ? 0.f : exp2f(d0[1] * EXPC) * inv0;
            float p2 = (mb0 & 1) ? 0.f : exp2f(d0[2] * EXPC) * inv1;
            float p3 = (mb0 & 2) ? 0.f : exp2f(d0[3] * EXPC) * inv1;
            float p4 = (ma1 & 1) ? 0.f : exp2f(d1[0] * EXPC) * inv0;
            float p5 = (ma1 & 2) ? 0.f : exp2f(d1[1] * EXPC) * inv0;
            float p6 = (mb1 & 1) ? 0.f : exp2f(d1[2] * EXPC) * inv1;
            float p7 = (mb1 & 2) ? 0.f : exp2f(d1[3] * EXPC) * inv1;
            // attention output
            float* a0 = att + (size_t)(q0 + r0) * SS + t * 64 + 16 * u + cq;
            *(float2*)a0 = make_float2(p0, p1);
            *(float2*)(a0 + 8 * (size_t)SS) = make_float2(p2, p3);
            *(float2*)(a0 + 8) = make_float2(p4, p5);
            *(float2*)(a0 + 8 * (size_t)SS + 8) = make_float2(p6, p7);
            // E fragment (A layout), one 16-key slice
            uint32_t eh[4], el[4];
            eh[0] = pack2hi(p0, p1); eh[1] = pack2hi(p2, p3);
            eh[2] = pack2hi(p4, p5); eh[3] = pack2hi(p6, p7);
            el[0] = pack2lo(p0, p1); el[1] = pack2lo(p2, p3);
            el[2] = pack2lo(p4, p5); el[3] = pack2lo(p6, p7);
            // PV for this slice
            #pragma unroll
            for (int nt = 0; nt < 8; nt++) {
                uint4 vb = *(const uint4*)(Vb + ((nt * 4 + u) * 32 + lane) * 16);
                mma_bf16(dacc[nt], eh, vb.x, vb.y);
                mma_bf16(dacc[nt], el, vb.x, vb.y);
                mma_bf16(dacc[nt], eh, vb.z, vb.w);
            }
        }
        __syncthreads();
    }

    // context epilogue (probs already normalized)
    float* ctx = out + (size_t)head * SS * DD;
    #pragma unroll
    for (int nt = 0; nt < 8; nt++) {
        const int col = 8 * nt + cq;
        *(float2*)(ctx + (size_t)(q0 + r0) * DD + col)     = make_float2(dacc[nt][0], dacc[nt][1]);
        *(float2*)(ctx + (size_t)(q0 + r0 + 8) * DD + col) = make_float2(dacc[nt][2], dacc[nt][3]);
    }
}

extern "C" void kernel_launch(void* const* d_in, const int* in_sizes, int n_in,
                              void* d_out, int out_size)
{
    (void)in_sizes; (void)n_in; (void)out_size;
    const float* Q = (const float*)d_in[0];
    const float* K = (const float*)d_in[1];
    const float* V = (const float*)d_in[2];
    const int*   M = (const int*)d_in[3];
    float* out = (float*)d_out;

    cudaFuncSetAttribute(attn_main,
                         cudaFuncAttributeMaxDynamicSharedMemorySize, SMEM_DYN);

    prepass_kernel<<<3584, NTHREADS>>>(Q, K, V, M);
    attn_main<<<NHEADS * 16, NTHREADS, SMEM_DYN>>>(out);
}

// round 16
// speedup vs baseline: 1.5660x; 1.2468x over previous
#include <cuda_runtime.h>
#include <cuda_fp16.h>
#include <cstdint>

#define BB 2
#define HH 16
#define SS 2048
#define DD 64
#define NTHREADS 256
#define CTX_ELEMS (BB*HH*SS*DD)
#define NHEADS 32
#define NT64 32                // key tiles of 64
#define QTILE_BYTES 32768      // Q frag image per 128-row block (hi+lo)
#define KTILE 16384            // K frag image per 64-key tile (hi 8K + lo 8K)
#define VTILE 8192             // V frag image per 64-key tile (hi only)
#define SMEM_DYN 49152         // pass B: K pp [0,32K) + V pp [32K,48K)
#define EXPC 0.18033688011112042f   // 0.125 * log2(e)
#define MASK_WORDS (BB*SS*64)

__device__ __align__(16) unsigned char g_qf[(size_t)NHEADS*16*QTILE_BYTES];
__device__ __align__(16) unsigned char g_kf[(size_t)NHEADS*NT64*KTILE];
__device__ __align__(16) unsigned char g_vf[(size_t)NHEADS*NT64*VTILE];
__device__ __align__(16) unsigned int  g_maskbits[MASK_WORDS];

__device__ __forceinline__ uint32_t pack2hi(float a, float b) {
    __half ha = __float2half_rn(a), hb = __float2half_rn(b);
    return (uint32_t)__half_as_ushort(ha) | ((uint32_t)__half_as_ushort(hb) << 16);
}
__device__ __forceinline__ uint32_t pack2lo(float a, float b) {
    __half ha = __float2half_rn(a), hb = __float2half_rn(b);
    __half la = __float2half_rn(a - __half2float(ha));
    __half lb = __float2half_rn(b - __half2float(hb));
    return (uint32_t)__half_as_ushort(la) | ((uint32_t)__half_as_ushort(lb) << 16);
}

// ---- prepass: Q(512) K(1024) V(1024) mask(1024) blocks ----
__global__ void prepass_kernel(const float* __restrict__ Q,
                               const float* __restrict__ K,
                               const float* __restrict__ V,
                               const int* __restrict__ M)
{
    const int bx = blockIdx.x;
    if (bx >= 2560) {
        const int w = (bx - 2560) * NTHREADS + threadIdx.x;
        const int* src = M + (size_t)w * 32;
        unsigned int bits = 0;
        #pragma unroll
        for (int j = 0; j < 32; j++) bits |= (src[j] != 0 ? 1u : 0u) << j;
        g_maskbits[w] = bits;
        return;
    }
    if (bx < 512) {
        // Q frag image: chunk = head*16 + sub (128-row block), hi+lo
        const int chunk = bx, head = chunk >> 4, sub = chunk & 15;
        const float* S_ = Q + (size_t)head * SS * DD;
        uint32_t* dst = (uint32_t*)(g_qf + (size_t)chunk * QTILE_BYTES);
        for (int i = threadIdx.x; i < 8192; i += NTHREADS) {
            int word = i & 7, lane = (i >> 3) & 31, kt = (i >> 8) & 3, mt = i >> 10;
            int ai = word & 3; bool lo = word >= 4;
            int r = (lane >> 2) + ((ai & 1) ? 8 : 0);
            int c = (lane & 3) * 2 + ((ai >= 2) ? 8 : 0);
            int row = sub * 128 + mt * 16 + r, col = kt * 16 + c;
            float f0 = S_[(size_t)row * DD + col], f1 = S_[(size_t)row * DD + col + 1];
            dst[i] = lo ? pack2lo(f0, f1) : pack2hi(f0, f1);
        }
        return;
    }
    if (bx < 1536) {
        // K frag image: chunk = head*32 + sub; hi block [0,2048w), lo block [2048w,4096w)
        const int chunk = bx - 512, head = chunk >> 5, sub = chunk & 31;
        const float* S_ = K + (size_t)head * SS * DD;
        uint32_t* dst = (uint32_t*)(g_kf + (size_t)chunk * KTILE);
        for (int i = threadIdx.x; i < 2048; i += NTHREADS) {
            int word = i & 1, lane = (i >> 1) & 31, kt = (i >> 6) & 3, j = (i >> 8) & 7;
            int key = sub * 64 + j * 8 + (lane >> 2);
            int dim = kt * 16 + (lane & 3) * 2 + (word ? 8 : 0);
            float f0 = S_[(size_t)key * DD + dim], f1 = S_[(size_t)key * DD + dim + 1];
            dst[i] = pack2hi(f0, f1);
            dst[2048 + i] = pack2lo(f0, f1);
        }
        return;
    }
    {
        // V frag image (hi only): chunk = head*32 + sub
        const int chunk = bx - 1536, head = chunk >> 5, sub = chunk & 31;
        const float* S_ = V + (size_t)head * SS * DD;
        uint32_t* dst = (uint32_t*)(g_vf + (size_t)chunk * VTILE);
        for (int i = threadIdx.x; i < 2048; i += NTHREADS) {
            int word = i & 1, lane = (i >> 1) & 31, u = (i >> 6) & 3, nt = (i >> 8) & 7;
            int key = sub * 64 + u * 16 + (lane & 3) * 2 + (word ? 8 : 0);
            int dim = nt * 8 + (lane >> 2);
            float f0 = S_[(size_t)key * DD + dim], f1 = S_[(size_t)(key + 1) * DD + dim];
            dst[i] = pack2hi(f0, f1);
        }
    }
}

// ---- main ----
__device__ __forceinline__ uint32_t smem_u32(const void* p) {
    uint32_t a;
    asm("{ .reg .u64 t; cvta.to.shared.u64 t, %1; cvt.u32.u64 %0, t; }" : "=r"(a) : "l"(p));
    return a;
}
__device__ __forceinline__ void cp16(uint32_t s, const void* g) {
    asm volatile("cp.async.cg.shared.global [%0], [%1], 16;" :: "r"(s), "l"(g));
}
__device__ __forceinline__ void mma_f16(float d[4], const uint32_t a[4],
                                        uint32_t b0, uint32_t b1) {
    asm volatile("mma.sync.aligned.m16n8k16.row.col.f32.f16.f16.f32 "
        "{%0,%1,%2,%3}, {%4,%5,%6,%7}, {%8,%9}, {%0,%1,%2,%3};"
        : "+f"(d[0]), "+f"(d[1]), "+f"(d[2]), "+f"(d[3])
        : "r"(a[0]), "r"(a[1]), "r"(a[2]), "r"(a[3]), "r"(b0), "r"(b1));
}

__global__ __launch_bounds__(NTHREADS, 2)
void attn_main(float* __restrict__ out)
{
    extern __shared__ unsigned char smem[];
    __shared__ float sSum[128];
    const uint32_t sb = smem_u32(smem);
    const int tid = threadIdx.x, w = tid >> 5, lane = tid & 31;
    const int head = blockIdx.x >> 4, qblk = blockIdx.x & 15;
    const int b = head >> 4;
    const int q0 = qblk * 128;
    const int r0 = 16 * w + (lane >> 2);
    const int cq = (lane & 3) * 2;

    // Q fragments resident (fp16 hi/lo)
    uint32_t qh[4][4], ql[4][4];
    {
        const unsigned char* qc = g_qf + (size_t)(head * 16 + qblk) * QTILE_BYTES;
        #pragma unroll
        for (int kt = 0; kt < 4; kt++) {
            const unsigned char* p = qc + (size_t)(((w * 4 + kt) * 32 + lane) * 32);
            uint4 h = *(const uint4*)p, l = *(const uint4*)(p + 16);
            qh[kt][0] = h.x; qh[kt][1] = h.y; qh[kt][2] = h.z; qh[kt][3] = h.w;
            ql[kt][0] = l.x; ql[kt][1] = l.y; ql[kt][2] = l.z; ql[kt][3] = l.w;
        }
    }
    const unsigned char* mrow0 = (const unsigned char*)g_maskbits + (size_t)(b * SS + q0 + r0) * 256;
    const unsigned char* mrow1 = mrow0 + 8 * 256;
    const unsigned char* kbase = g_kf + (size_t)head * NT64 * KTILE;
    const unsigned char* vbase = g_vf + (size_t)head * NT64 * VTILE;

    // ================= pass A: rowsums (1-term fp16, K-hi only) =================
    {
        #pragma unroll
        for (int i = 0; i < 2; i++) cp16(sb + tid * 16 + i * 4096, kbase + tid * 16 + i * 4096);
        asm volatile("cp.async.commit_group;");
    }
    float rs0 = 0.f, rs1 = 0.f;
    for (int t = 0; t < NT64; t++) {
        if (t < NT64 - 1) {
            const unsigned char* src = kbase + (size_t)(t + 1) * KTILE;   // hi block first 8KB
            uint32_t d0 = sb + ((t + 1) & 1) * 8192;
            #pragma unroll
            for (int i = 0; i < 2; i++) cp16(d0 + tid * 16 + i * 4096, src + tid * 16 + i * 4096);
            asm volatile("cp.async.commit_group;");
            asm volatile("cp.async.wait_group 1;");
        } else {
            asm volatile("cp.async.wait_group 0;");
        }
        __syncthreads();
        const unsigned char* Kb = smem + (t & 1) * 8192;
        uint2 mA = *(const uint2*)(mrow0 + t * 8);
        uint2 mB = *(const uint2*)(mrow1 + t * 8);
        #pragma unroll
        for (int j = 0; j < 8; j++) {
            float d[4] = {0.f, 0.f, 0.f, 0.f};
            #pragma unroll
            for (int kt = 0; kt < 4; kt++) {
                uint2 bh = *(const uint2*)(Kb + ((j * 4 + kt) * 32 + lane) * 8);
                mma_f16(d, qh[kt], bh.x, bh.y);
            }
            const int sh = 8 * (j & 3) + cq;
            const uint32_t ma = ((j < 4) ? mA.x : mA.y) >> sh;
            const uint32_t mb2 = ((j < 4) ? mB.x : mB.y) >> sh;
            rs0 += ((ma  & 1) ? 0.f : exp2f(d[0] * EXPC)) + ((ma  & 2) ? 0.f : exp2f(d[1] * EXPC));
            rs1 += ((mb2 & 1) ? 0.f : exp2f(d[2] * EXPC)) + ((mb2 & 2) ? 0.f : exp2f(d[3] * EXPC));
        }
        __syncthreads();
    }
    rs0 += __shfl_xor_sync(0xFFFFFFFFu, rs0, 1); rs0 += __shfl_xor_sync(0xFFFFFFFFu, rs0, 2);
    rs1 += __shfl_xor_sync(0xFFFFFFFFu, rs1, 1); rs1 += __shfl_xor_sync(0xFFFFFFFFu, rs1, 2);
    if ((lane & 3) == 0) { sSum[r0] = rs0; sSum[r0 + 8] = rs1; }
    __syncthreads();
    const float inv0 = 1.0f / sSum[r0];
    const float inv1 = 1.0f / sSum[r0 + 8];

    // ================= pass B: QK 3-term + att + PV 2-term =================
    float dacc[8][4];
    #pragma unroll
    for (int nt = 0; nt < 8; nt++) { dacc[nt][0]=0.f; dacc[nt][1]=0.f; dacc[nt][2]=0.f; dacc[nt][3]=0.f; }
    {
        #pragma unroll
        for (int i = 0; i < 4; i++) cp16(sb + tid * 16 + i * 4096, kbase + tid * 16 + i * 4096);
        #pragma unroll
        for (int i = 0; i < 2; i++) cp16(sb + 32768 + tid * 16 + i * 4096, vbase + tid * 16 + i * 4096);
        asm volatile("cp.async.commit_group;");
    }
    float* att = out + (size_t)CTX_ELEMS + (size_t)head * SS * SS;
    for (int t = 0; t < NT64; t++) {
        if (t < NT64 - 1) {
            const unsigned char* sk = kbase + (size_t)(t + 1) * KTILE;
            const unsigned char* sv = vbase + (size_t)(t + 1) * VTILE;
            uint32_t dk = sb + ((t + 1) & 1) * 16384;
            uint32_t dv = sb + 32768 + ((t + 1) & 1) * 8192;
            #pragma unroll
            for (int i = 0; i < 4; i++) cp16(dk + tid * 16 + i * 4096, sk + tid * 16 + i * 4096);
            #pragma unroll
            for (int i = 0; i < 2; i++) cp16(dv + tid * 16 + i * 4096, sv + tid * 16 + i * 4096);
            asm volatile("cp.async.commit_group;");
            asm volatile("cp.async.wait_group 1;");
        } else {
            asm volatile("cp.async.wait_group 0;");
        }
        __syncthreads();
        const unsigned char* Kb = smem + (t & 1) * 16384;   // hi at +0, lo at +8192
        const unsigned char* Vb = smem + 32768 + (t & 1) * 8192;
        uint2 mA = *(const uint2*)(mrow0 + t * 8);
        uint2 mB = *(const uint2*)(mrow1 + t * 8);
        #pragma unroll
        for (int u = 0; u < 4; u++) {
            const int j0 = 2 * u, j1 = 2 * u + 1;
            float d0[4] = {0.f,0.f,0.f,0.f}, d1[4] = {0.f,0.f,0.f,0.f};
            #pragma unroll
            for (int kt = 0; kt < 4; kt++) {
                uint2 bh0 = *(const uint2*)(Kb + ((j0 * 4 + kt) * 32 + lane) * 8);
                uint2 bl0 = *(const uint2*)(Kb + 8192 + ((j0 * 4 + kt) * 32 + lane) * 8);
                mma_f16(d0, qh[kt], bh0.x, bh0.y);
                mma_f16(d0, ql[kt], bh0.x, bh0.y);
                mma_f16(d0, qh[kt], bl0.x, bl0.y);
                uint2 bh1 = *(const uint2*)(Kb + ((j1 * 4 + kt) * 32 + lane) * 8);
                uint2 bl1 = *(const uint2*)(Kb + 8192 + ((j1 * 4 + kt) * 32 + lane) * 8);
                mma_f16(d1, qh[kt], bh1.x, bh1.y);
                mma_f16(d1, ql[kt], bh1.x, bh1.y);
                mma_f16(d1, qh[kt], bl1.x, bl1.y);
            }
            const int sh0 = 8 * (j0 & 3) + cq, sh1 = 8 * (j1 & 3) + cq;
            const uint32_t ma0 = ((j0 < 4) ? mA.x : mA.y) >> sh0;
            const uint32_t mb0 = ((j0 < 4) ? mB.x : mB.y) >> sh0;
            const uint32_t ma1 = ((j1 < 4) ? mA.x : mA.y) >> sh1;
            const uint32_t mb1 = ((j1 < 4) ? mB.x : mB.y) >> sh1;
            float p0 = (ma0 & 1) ? 0.f : exp2f(d0[0] * EXPC) * inv0;
            float p1 = (ma0 & 2) ? 0.f : exp2f(d0[1] * EXPC) * inv0;
            float p2 = (mb0 & 1) ? 0.f : exp2f(d0[2] * EXPC) * inv1;
            float p3 = (mb0 & 2) ? 0.f : exp2f(d0[3] * EXPC) * inv1;
            float p4 = (ma1 & 1) ? 0.f : exp2f(d1[0] * EXPC) * inv0;
            float p5 = (ma1 & 2) ? 0.f : exp2f(d1[1] * EXPC) * inv0;
            float p6 = (mb1 & 1) ? 0.f : exp2f(d1[2] * EXPC) * inv1;
            float p7 = (mb1 & 2) ? 0.f : exp2f(d1[3] * EXPC) * inv1;
            // attention output
            float* a0 = att + (size_t)(q0 + r0) * SS + t * 64 + 16 * u + cq;
            *(float2*)a0 = make_float2(p0, p1);
            *(float2*)(a0 + 8 * (size_t)SS) = make_float2(p2, p3);
            *(float2*)(a0 + 8) = make_float2(p4, p5);
            *(float2*)(a0 + 8 * (size_t)SS + 8) = make_float2(p6, p7);
            // E fragment (A layout), fp16 hi/lo
            uint32_t eh[4], el[4];
            eh[0] = pack2hi(p0, p1); eh[1] = pack2hi(p2, p3);
            eh[2] = pack2hi(p4, p5); eh[3] = pack2hi(p6, p7);
            el[0] = pack2lo(p0, p1); el[1] = pack2lo(p2, p3);
            el[2] = pack2lo(p4, p5); el[3] = pack2lo(p6, p7);
            // PV 2-term: (eh + el) x vh
            #pragma unroll
            for (int nt = 0; nt < 8; nt++) {
                uint2 vb = *(const uint2*)(Vb + ((nt * 4 + u) * 32 + lane) * 8);
                mma_f16(dacc[nt], eh, vb.x, vb.y);
                mma_f16(dacc[nt], el, vb.x, vb.y);
            }
        }
        __syncthreads();
    }

    // context epilogue (probs already normalized)
    float* ctx = out + (size_t)head * SS * DD;
    #pragma unroll
    for (int nt = 0; nt < 8; nt++) {
        const int col = 8 * nt + cq;
        *(float2*)(ctx + (size_t)(q0 + r0) * DD + col)     = make_float2(dacc[nt][0], dacc[nt][1]);
        *(float2*)(ctx + (size_t)(q0 + r0 + 8) * DD + col) = make_float2(dacc[nt][2], dacc[nt][3]);
    }
}

extern "C" void kernel_launch(void* const* d_in, const int* in_sizes, int n_in,
                              void* d_out, int out_size)
{
    (void)in_sizes; (void)n_in; (void)out_size;
    const float* Q = (const float*)d_in[0];
    const float* K = (const float*)d_in[1];
    const float* V = (const float*)d_in[2];
    const int*   M = (const int*)d_in[3];
    float* out = (float*)d_out;

    cudaFuncSetAttribute(attn_main,
                         cudaFuncAttributeMaxDynamicSharedMemorySize, SMEM_DYN);

    prepass_kernel<<<3584, NTHREADS>>>(Q, K, V, M);
    attn_main<<<NHEADS * 16, NTHREADS, SMEM_DYN>>>(out);
}